// round 17
// baseline (speedup 1.0000x reference)
#include <cuda_runtime.h>
#include <cstdint>
#include <math.h>

#define SIGMA_C 0.14f
#define R0_C    50.0f
#define DT_C    0.1f
#define NT_C    2000
#define B_C     4096

#define TABN   1024
#define NNODES (TABN + 2)
#define JMAX_C 3.5f
#define INVH_F ((float)TABN / JMAX_C)
#define MAGIC_F 12582912.0f

#define T_FROZEN 112
#define TILE_S   32
#define NTILES_A ((NT_C - T_FROZEN) / TILE_S)    // 59
#define QLEN 272
#define EPB  64                                  // elements per CTA

__device__ float g_nodes[NNODES];

#define NODE_BLOCKS ((NNODES + 31) / 32)      // 33

__global__ void __launch_bounds__(128)
build_nodes_kernel(const float* __restrict__ W1, const float* __restrict__ b1,
                   const float* __restrict__ W2, const float* __restrict__ b2,
                   const float* __restrict__ W3, const float* __restrict__ b3) {
    const int tid = threadIdx.x;
    __shared__ float sW2[64 * 64];
    __shared__ float sh1[32][65];
    {
        const float4* src = reinterpret_cast<const float4*>(W2);
        float4* dst = reinterpret_cast<float4*>(sW2);
#pragma unroll
        for (int q = 0; q < 8; ++q) dst[tid + 128 * q] = __ldg(src + tid + 128 * q);
    }
    const int nl = tid >> 2, c = tid & 3;
    const int node = blockIdx.x * 32 + nl;
    const float x = (float)(node - 1) * (JMAX_C / (float)TABN);
#pragma unroll
    for (int k = 0; k < 16; ++k) {
        const int u = c * 16 + k;
        sh1[nl][u] = fmaxf(fmaf(x, __ldg(W1 + u), __ldg(b1 + u)), 0.0f);
    }
    __syncthreads();
    float acc[16];
#pragma unroll
    for (int k = 0; k < 16; ++k) acc[k] = __ldg(b2 + c * 16 + k);
#pragma unroll 4
    for (int j = 0; j < 64; ++j) {
        const float hj = sh1[nl][j];
        const float4* row = reinterpret_cast<const float4*>(sW2 + j * 64 + c * 16);
#pragma unroll
        for (int q = 0; q < 4; ++q) {
            const float4 w = row[q];
            acc[q*4+0] = fmaf(hj, w.x, acc[q*4+0]);
            acc[q*4+1] = fmaf(hj, w.y, acc[q*4+1]);
            acc[q*4+2] = fmaf(hj, w.z, acc[q*4+2]);
            acc[q*4+3] = fmaf(hj, w.w, acc[q*4+3]);
        }
    }
    float part = 0.0f;
#pragma unroll
    for (int k = 0; k < 16; ++k)
        part = fmaf(fmaxf(acc[k], 0.0f), __ldg(W3 + c * 16 + k), part);
    part += __shfl_down_sync(0xFFFFFFFFu, part, 2);
    part += __shfl_down_sync(0xFFFFFFFFu, part, 1);
    if (c == 0 && node < NNODES) g_nodes[node] = part + __ldg(b3);
}

// smem layout
#define TAB_BYTES  (NNODES * 8)                // 8208
#define Q_OFF      TAB_BYTES
#define BUF_OFF    9344
#define BUF_ARR    8192                        // 64 rows * 128B
#define BUF_P      (3 * BUF_ARR)               // 24576
#define SMEM_TOTAL (BUF_OFF + 2 * BUF_P)       // 58496

extern __shared__ char smem_raw[];

__device__ __forceinline__ uint32_t smem_u32(const void* p) {
    uint32_t a;
    asm("{ .reg .u64 t; cvta.to.shared.u64 t, %1; cvt.u32.u64 %0, t; }"
        : "=r"(a) : "l"(p));
    return a;
}
__device__ __forceinline__ void sts128(uint32_t a, float x, float y, float z, float w) {
    asm volatile("st.shared.v4.f32 [%0], {%1, %2, %3, %4};"
                 :: "r"(a), "f"(x), "f"(y), "f"(z), "f"(w) : "memory");
}
__device__ __forceinline__ float4 lds128(uint32_t a) {
    float4 v;
    asm volatile("ld.shared.v4.f32 {%0, %1, %2, %3}, [%4];"
                 : "=f"(v.x), "=f"(v.y), "=f"(v.z), "=f"(v.w) : "r"(a));
    return v;
}
__device__ __forceinline__ void lds64(uint32_t a, float& x, float& y) {
    asm volatile("ld.shared.v2.f32 {%0, %1}, [%2];" : "=f"(x), "=f"(y) : "r"(a));
}
#define BAR_SYNC(id)   asm volatile("bar.sync %0, 64;"   :: "r"(id) : "memory")
#define BAR_ARRIVE(id) asm volatile("bar.arrive %0, 64;" :: "r"(id) : "memory")

__device__ __forceinline__ float q_inc(float tf) {
    return __fmul_rn(__fmul_rn(__fmul_rn(SIGMA_C, __fmul_rn(DT_C, tf)),
                               0.125f), DT_C);
}

// ---------------- per-element chain state ----------------
struct Ch {
    float res, thk, u, den_prev, dif_prev, tcp;
    float p0, q0, p1, q1, c00, c10, c01, c11;
    float cvde0, mjc0, cvde1, mjc1;
    float cvdt, mjcC;
    int   tstar;
};

__device__ __forceinline__ void trans_step(Ch& c, int t2abs, uint32_t tabC,
                                           float& o0, float& o1, float& o2) {
    const float dd  = fmaf(c.dif_prev, 3.0f, c.den_prev);
    const float tN  = fmaf(dd, -c.u, 2.0f);
    const float u2  = __fmul_rn(c.u, tN);
    const float nu2 = __fmul_rn(c.tcp, __fmul_rn(u2, 0.014f));
    const float p2  = __fmul_rn(nu2, u2);
    const float q2  = __fmul_rn(nu2, 2.0f);
    const float m   = fmaf(nu2, INVH_F, MAGIC_F);
    float na, nb;
    lds64((__float_as_uint(m) << 3) + tabC, na, nb);
    const bool  a2  = (t2abs >= c.tstar);
    const float cd2 = a2 ? c.cvdt : 0.0f;
    const float mj2 = a2 ? c.mjcC : 0.0f;
    c.u = u2; c.tcp += 1.0f;
    const float resin = c.res;
    const float den = fmaf(resin, SIGMA_C, 1.0f);
    const float jv  = fmaf(den, -c.p0, c.q0);
    const float rho = fmaf(jv, c.c10, c.c00);
    const float jd  = fmaf(jv, c.cvde0, c.mjc0);      // frozen: exactly 0
    c.res = fmaxf(fmaf(rho, jd, resin), R0_C);
    c.thk = fmaxf(c.thk + jd, 0.0f);
    o0 = c.thk; o1 = c.res; o2 = jv;
    c.dif_prev = den - c.den_prev;  c.den_prev = den;
    c.p0 = c.p1; c.q0 = c.q1; c.p1 = p2; c.q1 = q2;
    c.c00 = c.c01; c.c10 = c.c11; c.c01 = na; c.c11 = nb;
    c.cvde0 = c.cvde1; c.mjc0 = c.mjc1; c.cvde1 = cd2; c.mjc1 = mj2;
}

__device__ __forceinline__ void steady_pair(Ch& c, float tslot, uint32_t tabC,
        float& a0, float& a1, float& a2, float& b0, float& b1, float& b2) {
    const float dd = fmaf(c.dif_prev, 3.5f, c.den_prev);
    const float tN = fmaf(dd, -c.u, 2.0f);
    c.u = __fmul_rn(c.u, tN);
    const float numA = __fmul_rn(tslot, 0.014f);
    const float numB = fmaf(tslot, 0.014f, 0.014f);
    const float nuA = __fmul_rn(numA, c.u), nuB = __fmul_rn(numB, c.u);
    const float pA = __fmul_rn(nuA, c.u),  pB = __fmul_rn(nuB, c.u);
    const float qA = __fmul_rn(nuA, 2.0f), qB = __fmul_rn(nuB, 2.0f);
    const float mA = fmaf(nuA, INVH_F, MAGIC_F);
    const float mB = fmaf(nuB, INVH_F, MAGIC_F);
    float nA0, nA1, nB0, nB1;
    lds64((__float_as_uint(mA) << 3) + tabC, nA0, nA1);
    lds64((__float_as_uint(mB) << 3) + tabC, nB0, nB1);
    // step even
    const float r0 = c.res;
    const float den0 = fmaf(r0, SIGMA_C, 1.0f);
    const float jv0  = fmaf(den0, -c.p0, c.q0);
    const float rho0 = fmaf(jv0, c.c10, c.c00);
    const float jd0  = fmaf(jv0, c.cvdt, c.mjcC);
    c.res = fmaxf(fmaf(rho0, jd0, r0), R0_C);
    c.thk = fmaxf(c.thk + jd0, 0.0f);
    a0 = c.thk; a1 = c.res; a2 = jv0;
    // step odd
    const float r1 = c.res;
    const float den1 = fmaf(r1, SIGMA_C, 1.0f);
    const float jv1  = fmaf(den1, -c.p1, c.q1);
    const float rho1 = fmaf(jv1, c.c11, c.c01);
    const float jd1  = fmaf(jv1, c.cvdt, c.mjcC);
    c.res = fmaxf(fmaf(rho1, jd1, r1), R0_C);
    c.thk = fmaxf(c.thk + jd1, 0.0f);
    b0 = c.thk; b1 = c.res; b2 = jv1;
    c.dif_prev = __fadd_rn(den1, -den0);  c.den_prev = den1;
    c.p0 = pA; c.q0 = qA; c.c00 = nA0; c.c10 = nA1;
    c.p1 = pB; c.q1 = qB; c.c01 = nB0; c.c11 = nB1;
}

__global__ void __launch_bounds__(64, 1)
simulate_kernel(const float* __restrict__ Cv, const float* __restrict__ Kp,
                const float* __restrict__ jminp, float* __restrict__ out) {
    const int tid  = threadIdx.x;
    const int lane = tid & 31;
    const int wid  = tid >> 5;

    float2* s_tab = reinterpret_cast<float2*>(smem_raw);
    float*  sQ    = reinterpret_cast<float*>(smem_raw + Q_OFF);

    {
        const int k0 = tid * (TABN / 64);
        float nm = __ldg(g_nodes + k0);
        float nc = __ldg(g_nodes + k0 + 1);
#pragma unroll 8
        for (int k = k0; k < k0 + TABN / 64; ++k) {
            const float np = __ldg(g_nodes + k + 2);
            const float slope = 0.5f * (np - nm);
            s_tab[k] = make_float2(fmaf(-slope, (float)k, nc), slope * INVH_F);
            nm = nc; nc = np;
        }
        if (tid == 63) {
            s_tab[TABN]     = s_tab[TABN - 1];
            s_tab[TABN + 1] = s_tab[TABN - 1];
        }
    }
    __syncthreads();

    const uint32_t tab32 = smem_u32(s_tab);
    const uint32_t tabC  = tab32 - 0x5A000000u;
    const uint32_t buf32 = smem_u32(smem_raw + BUF_OFF);
    const int e0 = blockIdx.x * EPB;

    if (wid == 1) {
        // =================== writer warp (coalesced, 64 rows) ===============
        BAR_ARRIVE(3); BAR_ARRIVE(4);
        float* oth0 = out + (size_t)e0 * NT_C;
        float* ore0 = oth0 + (size_t)B_C * NT_C;
        float* ocu0 = ore0 + (size_t)B_C * NT_C;
        float* oti0 = ocu0 + (size_t)B_C * NT_C;
        const int elw = lane >> 3, ch = lane & 7;

        // frozen region [0, 112): closed form
#pragma unroll
        for (int eg = 0; eg < 16; ++eg) {
            const int el = eg * 4 + elw;
            const size_t ro = (size_t)el * NT_C;
#pragma unroll
            for (int cc = 0; cc < 4; ++cc) {
                const int chunk = cc * 8 + ch;
                if (chunk < T_FROZEN / 4) {
                    const int t0 = chunk * 4;
                    const float tf = (float)t0;
                    float j0 = __fmul_rn(tf, 0.00175f);
                    if (t0 == 0) j0 = 1e-3f;
                    *reinterpret_cast<float4*>(oth0 + ro + t0) =
                        make_float4(0.f, 0.f, 0.f, 0.f);
                    *reinterpret_cast<float4*>(ore0 + ro + t0) =
                        make_float4(R0_C, R0_C, R0_C, R0_C);
                    *reinterpret_cast<float4*>(ocu0 + ro + t0) =
                        make_float4(j0, __fmul_rn(tf + 1.0f, 0.00175f),
                                    __fmul_rn(tf + 2.0f, 0.00175f),
                                    __fmul_rn(tf + 3.0f, 0.00175f));
                    *reinterpret_cast<float4*>(oti0 + ro + t0) =
                        make_float4(__fmul_rn(DT_C, tf),
                                    __fmul_rn(DT_C, tf + 1.0f),
                                    __fmul_rn(DT_C, tf + 2.0f),
                                    __fmul_rn(DT_C, tf + 3.0f));
                }
            }
        }

        for (int tile = 0; tile < NTILES_A; ++tile) {
            const int p = tile & 1;
            BAR_SYNC(1 + p);
            const uint32_t bp = buf32 + p * BUF_P;
            const int base = T_FROZEN + tile * TILE_S;
            const float tq0 = (float)(base + ch * 4);
            const float4 tv = make_float4(__fmul_rn(DT_C, tq0),
                                          __fmul_rn(DT_C, tq0 + 1.0f),
                                          __fmul_rn(DT_C, tq0 + 2.0f),
                                          __fmul_rn(DT_C, tq0 + 3.0f));
#pragma unroll
            for (int eg = 0; eg < 16; ++eg) {
                const int el = eg * 4 + elw;
                const uint32_t sa = bp + (uint32_t)el * 128u
                                  + (uint32_t)((ch ^ (el & 7)) << 4);
                const float4 a = lds128(sa + 0 * BUF_ARR);
                const float4 b = lds128(sa + 1 * BUF_ARR);
                const float4 c = lds128(sa + 2 * BUF_ARR);
                const size_t go = (size_t)el * NT_C + base + ch * 4;
                *reinterpret_cast<float4*>(oth0 + go) = a;
                *reinterpret_cast<float4*>(ore0 + go) = b;
                *reinterpret_cast<float4*>(ocu0 + go) = c;
                *reinterpret_cast<float4*>(oti0 + go) = tv;
            }
            BAR_ARRIVE(3 + p);
        }
        return;
    }

    // =================== compute warp ===================
    {
        float Q = 0.0f;
        if (lane == 0) sQ[0] = 0.0f;
        for (int t = 1; t < QLEN; t += 4) {
            const float f0 = (float)t;
            const float i0 = q_inc(f0), i1 = q_inc(f0 + 1.0f);
            const float i2 = q_inc(f0 + 2.0f), i3 = q_inc(f0 + 3.0f);
            Q = __fadd_rn(Q, i0); if (lane == 0) sQ[t]     = Q;
            Q = __fadd_rn(Q, i1); if (lane == 0) sQ[t + 1] = Q;
            Q = __fadd_rn(Q, i2); if (lane == 0) sQ[t + 2] = Q;
            Q = __fadd_rn(Q, i3); if (lane == 0) sQ[t + 3] = Q;
        }
    }
    __syncwarp();

    const double beta_d = 0.14 * 1.0 / (0.14 * 50.0 + 1.0);
    const float CQ = (float)pow(81.0 / (128.0 * beta_d), 1.0 / 3.0);

    Ch X, Y;
    int tmax2 = 0;
#pragma unroll
    for (int h = 0; h < 2; ++h) {
        const int e = e0 + h * 32 + lane;
        const float kk = __ldg(Kp + e);
        const float Qmin = CQ * powf(kk, 4.0f / 3.0f);
        int lo = 0, hi = QLEN;
        while (hi - lo > 1) {
            const int mid = (lo + hi) >> 1;
            if (sQ[mid] <= Qmin) lo = mid; else hi = mid;
        }
        Ch& c = h ? Y : X;
        c.tstar = hi;
        tmax2 = max(tmax2, hi);
        const float cv  = __ldg(Cv + e);
        const float jmn = __ldg(jminp + e);
        c.cvdt = __fmul_rn(cv, DT_C);
        c.mjcC = __fmul_rn(-jmn, c.cvdt);
        c.res = R0_C; c.thk = 0.0f; c.u = 0.125f;
        c.den_prev = 8.0f; c.dif_prev = 0.0f; c.tcp = 114.0f;
        const float nuA0 = __fmul_rn(__fmul_rn(112.0f, 0.014f), 0.125f);
        const float nuB0 = __fmul_rn(__fmul_rn(113.0f, 0.014f), 0.125f);
        c.p0 = __fmul_rn(nuA0, 0.125f); c.q0 = __fmul_rn(nuA0, 2.0f);
        c.p1 = __fmul_rn(nuB0, 0.125f); c.q1 = __fmul_rn(nuB0, 2.0f);
#pragma unroll
        for (int k = 0; k < 2; ++k) {
            const float jk = __fmul_rn(112.0f + (float)k, 0.00175f);
            const float m  = fmaf(jk, INVH_F, MAGIC_F);
            uint32_t iu = __float_as_uint(m) & 0x3FFFFFu;
            iu = min(iu, (uint32_t)(TABN - 1));
            const float2 te = s_tab[iu];
            if (k == 0) { c.c00 = te.x; c.c10 = te.y; }
            else        { c.c01 = te.x; c.c11 = te.y; }
        }
        c.cvde0 = 0.0f; c.mjc0 = 0.0f; c.cvde1 = 0.0f; c.mjc1 = 0.0f;
    }
    const int tmax = __reduce_max_sync(0xFFFFFFFFu, tmax2);
    int steadyTile = (tmax + 2 - T_FROZEN + TILE_S - 1) / TILE_S;
    if (steadyTile > NTILES_A) steadyTile = NTILES_A;

    const uint32_t row_l = buf32 + (uint32_t)lane * 128u;          // chain X row
    const uint32_t row_h = buf32 + (uint32_t)(lane + 32) * 128u;   // chain Y row
    const uint32_t sw_l  = (uint32_t)((lane & 7) << 4);
    float sthX[4], sreX[4], scuX[4], sthY[4], sreY[4], scuY[4];

    int tile = 0;
    // -------- transition tiles --------
    for (; tile < steadyTile; ++tile) {
        const int p = tile & 1;
        BAR_SYNC(3 + p);
        const uint32_t bpx = row_l + p * BUF_P;
        const uint32_t bpy = row_h + p * BUF_P;
        const int base = T_FROZEN + tile * TILE_S;
#pragma unroll
        for (int s = 0; s < TILE_S; ++s) {
            trans_step(X, base + s + 2, tabC,
                       sthX[s & 3], sreX[s & 3], scuX[s & 3]);
            trans_step(Y, base + s + 2, tabC,
                       sthY[s & 3], sreY[s & 3], scuY[s & 3]);
            if ((s & 3) == 3) {
                const uint32_t co = (uint32_t)(((s >> 2) << 4)) ^ sw_l;
                sts128(bpx + 0 * BUF_ARR + co, sthX[0], sthX[1], sthX[2], sthX[3]);
                sts128(bpx + 1 * BUF_ARR + co, sreX[0], sreX[1], sreX[2], sreX[3]);
                sts128(bpx + 2 * BUF_ARR + co, scuX[0], scuX[1], scuX[2], scuX[3]);
                sts128(bpy + 0 * BUF_ARR + co, sthY[0], sthY[1], sthY[2], sthY[3]);
                sts128(bpy + 1 * BUF_ARR + co, sreY[0], sreY[1], sreY[2], sreY[3]);
                sts128(bpy + 2 * BUF_ARR + co, scuY[0], scuY[1], scuY[2], scuY[3]);
            }
        }
        BAR_ARRIVE(1 + p);
    }

    // -------- steady tiles: paired prep, two interleaved chains --------
    float tslot = (float)(T_FROZEN + steadyTile * TILE_S + 2);
    for (; tile < NTILES_A; ++tile) {
        const int p = tile & 1;
        BAR_SYNC(3 + p);
        const uint32_t bpx = row_l + p * BUF_P;
        const uint32_t bpy = row_h + p * BUF_P;
#pragma unroll
        for (int s = 0; s < TILE_S; s += 2) {
            steady_pair(X, tslot, tabC,
                        sthX[s & 3], sreX[s & 3], scuX[s & 3],
                        sthX[(s + 1) & 3], sreX[(s + 1) & 3], scuX[(s + 1) & 3]);
            steady_pair(Y, tslot, tabC,
                        sthY[s & 3], sreY[s & 3], scuY[s & 3],
                        sthY[(s + 1) & 3], sreY[(s + 1) & 3], scuY[(s + 1) & 3]);
            tslot += 2.0f;
            if ((s & 3) == 2) {
                const uint32_t co = (uint32_t)(((s >> 2) << 4)) ^ sw_l;
                sts128(bpx + 0 * BUF_ARR + co, sthX[0], sthX[1], sthX[2], sthX[3]);
                sts128(bpx + 1 * BUF_ARR + co, sreX[0], sreX[1], sreX[2], sreX[3]);
                sts128(bpx + 2 * BUF_ARR + co, scuX[0], scuX[1], scuX[2], scuX[3]);
                sts128(bpy + 0 * BUF_ARR + co, sthY[0], sthY[1], sthY[2], sthY[3]);
                sts128(bpy + 1 * BUF_ARR + co, sreY[0], sreY[1], sreY[2], sreY[3]);
                sts128(bpy + 2 * BUF_ARR + co, scuY[0], scuY[1], scuY[2], scuY[3]);
            }
        }
        BAR_ARRIVE(1 + p);
    }
}

extern "C" void kernel_launch(void* const* d_in, const int* in_sizes, int n_in,
                              void* d_out, int out_size) {
    const float* Cv = (const float*)d_in[0];
    const float* K  = (const float*)d_in[1];
    const float* jm = (const float*)d_in[2];
    const float* W1 = (const float*)d_in[3];
    const float* b1 = (const float*)d_in[4];
    const float* W2 = (const float*)d_in[5];
    const float* b2 = (const float*)d_in[6];
    const float* W3 = (const float*)d_in[7];
    const float* b3 = (const float*)d_in[8];
    float* out = (float*)d_out;

    build_nodes_kernel<<<NODE_BLOCKS, 128>>>(W1, b1, W2, b2, W3, b3);

    cudaFuncSetAttribute(simulate_kernel,
                         cudaFuncAttributeMaxDynamicSharedMemorySize, SMEM_TOTAL);
    simulate_kernel<<<B_C / EPB, 64, SMEM_TOTAL>>>(Cv, K, jm, out);
}